// round 17
// baseline (speedup 1.0000x reference)
#include <cuda_runtime.h>
#include <cuda_fp16.h>
#include <cstdint>

#define B_ 64
#define S_ 2048
#define H_ 512

// ---------------- scratch (device globals; no allocation allowed) ----------
__device__ float g_c[B_ * H_];                       // e_fin[b,k] + attn_b[k]
__device__ float g_scores_part[4 * B_ * S_];         // per-k-tile partial scores
__device__ float g_weights[B_ * S_];                 // softmax weights
__device__ float g_ctx_part[16 * B_ * H_];           // per-s-chunk partial context
__device__ __half g_enc_hi[(size_t)B_ * S_ * H_];    // 128 MB (fp16)
__device__ __half g_w_hi[H_ * H_];

// ---------------- helpers ---------------------------------------------------
__device__ __forceinline__ uint32_t smem_u32(const void* p) {
    uint32_t a;
    asm("{ .reg .u64 t; cvta.to.shared.u64 t, %1; cvt.u32.u64 %0, t; }" : "=r"(a) : "l"(p));
    return a;
}
__device__ __forceinline__ void cp16(uint32_t dst, const void* src) {
    asm volatile("cp.async.cg.shared.global [%0], [%1], 16;" :: "r"(dst), "l"(src) : "memory");
}
#define CP_COMMIT() asm volatile("cp.async.commit_group;" ::: "memory")

__device__ __forceinline__ void ldsm4(uint32_t* r, uint32_t addr) {
    asm volatile("ldmatrix.sync.aligned.m8n8.x4.shared.b16 {%0,%1,%2,%3}, [%4];"
                 : "=r"(r[0]), "=r"(r[1]), "=r"(r[2]), "=r"(r[3]) : "r"(addr));
}
__device__ __forceinline__ void mma16816(float* d, const uint32_t* a,
                                         uint32_t b0, uint32_t b1) {
    asm volatile(
        "mma.sync.aligned.m16n8k16.row.col.f32.f16.f16.f32 "
        "{%0,%1,%2,%3}, {%4,%5,%6,%7}, {%8,%9}, {%0,%1,%2,%3};"
        : "+f"(d[0]), "+f"(d[1]), "+f"(d[2]), "+f"(d[3])
        : "r"(a[0]), "r"(a[1]), "r"(a[2]), "r"(a[3]), "r"(b0), "r"(b1));
}

__device__ __forceinline__ float fast_tanh(float x) {
    x = fminf(fmaxf(x, -15.f), 15.f);
    float e = __expf(2.f * x);
    return __fdividef(e - 1.f, e + 1.f);
}

// ---------------- K0a: enc f32 -> fp16 --------------------------------------
__global__ void convert_enc_kernel(const float* __restrict__ enc) {
    size_t i = (size_t)blockIdx.x * 256 + threadIdx.x;   // one float4 per thread
    float4 x = ((const float4*)enc)[i];
    __half2 h01 = __floats2half2_rn(x.x, x.y);
    __half2 h23 = __floats2half2_rn(x.z, x.w);
    uint2 packed;
    packed.x = *(const uint32_t*)&h01;
    packed.y = *(const uint32_t*)&h23;
    ((uint2*)g_enc_hi)[i] = packed;
}

// ---------------- K0b: w_enc f32 -> fp16 ------------------------------------
__global__ void convert_w_kernel(const float* __restrict__ attn_w) {
    int idx = blockIdx.x * 256 + threadIdx.x;            // 262144
    int k = idx >> 9, h = idx & 511;
    float x = attn_w[(size_t)k * (2 * H_) + h];          // w_enc = attn_w[:, :H]
    g_w_hi[idx] = __float2half_rn(x);
}

// ---------------- K1: c[b,k] = fin[b]·attn_w[k, H:] + b[k] ------------------
__global__ void cfin_kernel(const float* __restrict__ fin,
                            const float* __restrict__ attn_w,
                            const float* __restrict__ attn_b) {
    __shared__ float fs[H_];
    const int b = blockIdx.x;
    const int k = threadIdx.x;
    fs[k] = fin[b * H_ + k];
    __syncthreads();
    const float* w = attn_w + (size_t)k * (2 * H_) + H_;
    float s = attn_b[k];
#pragma unroll 8
    for (int h = 0; h < H_; h++) s = fmaf(fs[h], w[h], s);
    g_c[b * H_ + k] = s;
}

// ---------------- K2: fp16 mma GEMM + tanh/v epilogue -----------------------
// CTA 256(s) x 128(k); 16 warps as 4(M) x 4(N); warp tile 64x32 (R12 geometry,
// single chain). K=512 in 8 chunks of 64; 3-stage cp.async, fully unrolled,
// hoisted fill addressing; register epilogue.
static constexpr int KC = 64;                        // 64 fp16 = 128B rows
static constexpr int MAT_A  = 256 * 128;             // 32768 B (A: 256 x 64 fp16)
static constexpr int MAT_BT = 128 * 128;             // 16384 B (B: 128 x 64 fp16)
static constexpr int STAGE_B = MAT_A + MAT_BT;       // 49152
static constexpr int NSTAGE = 3;
static constexpr int CV_OFF = NSTAGE * STAGE_B;      // 147456
static constexpr int SMEM_NEED = CV_OFF + 1024;      // + c[128], v[128]

// physical byte offset of logical (row r, 16B-chunk c) inside a 128B-row tile
__device__ __forceinline__ uint32_t sw(int r, int c) {
    return (uint32_t)(r * 128 + (((c) ^ (r & 7)) << 4));
}

__global__ __launch_bounds__(512, 1)
void scores_mma_kernel(const float* __restrict__ v_w) {
    extern __shared__ char smem[];
    const uint32_t sbase = smem_u32(smem);
    const int tid = threadIdx.x;
    const int wid = tid >> 5, lane = tid & 31;
    const int kt = blockIdx.x;        // 0..3   (k tile of 128)
    const int mt = blockIdx.y;        // 0..511 (s tile of 256 over B*S)
    const int b  = mt >> 3;           // 8 s-tiles per batch
    const int wm = wid & 3;           // warp M index (4) -> 64 rows each
    const int wn = wid >> 2;          // warp N index (4) -> 32 cols each

    float* c_s = (float*)(smem + CV_OFF);
    float* v_s = (float*)(smem + CV_OFF + 512);
    if (tid < 128) {
        c_s[tid] = g_c[b * H_ + kt * 128 + tid];
        v_s[tid] = v_w[kt * 128 + tid];
    }

    float acc[4][4][4];
#pragma unroll
    for (int i = 0; i < 4; i++)
#pragma unroll
        for (int j = 0; j < 4; j++)
#pragma unroll
            for (int t = 0; t < 4; t++) acc[i][j][t] = 0.f;

    // ---- hoisted per-thread fill addressing (chunk-invariant) --------------
    uint32_t sA_off[4], gA_off[4];    // A: 4 cp16 per thread per chunk
    uint32_t sB_off[2], gB_off[2];    // B: 2 cp16 per thread per chunk
#pragma unroll
    for (int i = 0; i < 4; i++) {
        int id = i * 512 + tid;       // 0..2047
        int r = id >> 3, c = id & 7;  // r 0..255
        sA_off[i] = sw(r, c);
        gA_off[i] = (uint32_t)(r * 1024 + c * 16);
    }
#pragma unroll
    for (int i = 0; i < 2; i++) {
        int id = i * 512 + tid;       // 0..1023
        int r = id >> 3, c = id & 7;  // r 0..127
        sB_off[i] = (uint32_t)MAT_A + sw(r, c);
        gB_off[i] = (uint32_t)(r * 1024 + c * 16);
    }
    const char* gA = (const char*)g_enc_hi + (size_t)mt * 256 * 1024;
    const char* gB = (const char*)g_w_hi + (size_t)kt * 128 * 1024;

#define FILL_CHUNK(st, ck)                                                      \
    do {                                                                        \
        _Pragma("unroll")                                                       \
        for (int p = 0; p < 4; p++)                                             \
            cp16(sbase + (st) * STAGE_B + sA_off[p], gA + gA_off[p] + (ck) * 128); \
        _Pragma("unroll")                                                       \
        for (int p = 0; p < 2; p++)                                             \
            cp16(sbase + (st) * STAGE_B + sB_off[p], gB + gB_off[p] + (ck) * 128); \
        CP_COMMIT();                                                            \
    } while (0)

    FILL_CHUNK(0, 0);
    FILL_CHUNK(1, 1);

    const int lrow_a = wm * 64 + (lane & 15);
    const int lrow_b = wn * 32 + (lane & 15);
    const int lchi = lane >> 4;
    const int qv = lane & 7;
    uint32_t offv[4];
#pragma unroll
    for (int kk = 0; kk < 4; kk++) offv[kk] = (uint32_t)(((kk * 2 + lchi) ^ qv) << 4);

#pragma unroll
    for (int ck = 0; ck < 8; ck++) {
        const int buf = ck % 3;            // compile-time after unroll
        if (ck < 6) asm volatile("cp.async.wait_group 1;" ::: "memory");
        else        asm volatile("cp.async.wait_group 0;" ::: "memory");
        __syncthreads();
        if (ck + 2 < 8) FILL_CHUNK((ck + 2) % 3, ck + 2);

        const uint32_t stb = sbase + buf * STAGE_B;
        const uint32_t bA = stb + (uint32_t)(lrow_a * 128);
        const uint32_t bB = stb + (uint32_t)MAT_A + (uint32_t)(lrow_b * 128);

#pragma unroll
        for (int kk = 0; kk < 4; kk++) {
            uint32_t a[4][4], bb[2][4];
#pragma unroll
            for (int i = 0; i < 4; i++) ldsm4(a[i], bA + i * 2048 + offv[kk]);
#pragma unroll
            for (int j = 0; j < 2; j++) ldsm4(bb[j], bB + j * 2048 + offv[kk]);
#pragma unroll
            for (int i = 0; i < 4; i++)
#pragma unroll
                for (int j = 0; j < 2; j++) {
                    mma16816(acc[i][j * 2 + 0], a[i], bb[j][0], bb[j][2]);
                    mma16816(acc[i][j * 2 + 1], a[i], bb[j][1], bb[j][3]);
                }
        }
    }
#undef FILL_CHUNK

    // ---- register epilogue: tanh(e + c) * v, quad-shuffle + smem reduce ----
    // thread holds rows {wm*64 + i*16 + (lane>>2), +8}, cols
    // {wn*32 + (j>>1)*16 + (j&1)*8 + (lane&3)*2 + {0,1}} for j in 0..3.
    float c_v[8], v_v[8];
#pragma unroll
    for (int j = 0; j < 4; j++) {
        const int col = wn * 32 + (j >> 1) * 16 + (j & 1) * 8 + (lane & 3) * 2;
        c_v[2 * j]     = c_s[col];
        c_v[2 * j + 1] = c_s[col + 1];
        v_v[2 * j]     = v_s[col];
        v_v[2 * j + 1] = v_s[col + 1];
    }
    float* red = (float*)smem;   // 256 rows x 4 wn = 4KB (stages dead)
    __syncthreads();
#pragma unroll
    for (int i = 0; i < 4; i++) {
        float p0 = 0.f, p1 = 0.f;
#pragma unroll
        for (int j = 0; j < 4; j++) {
            p0 += fast_tanh(acc[i][j][0] + c_v[2 * j])     * v_v[2 * j];
            p0 += fast_tanh(acc[i][j][1] + c_v[2 * j + 1]) * v_v[2 * j + 1];
            p1 += fast_tanh(acc[i][j][2] + c_v[2 * j])     * v_v[2 * j];
            p1 += fast_tanh(acc[i][j][3] + c_v[2 * j + 1]) * v_v[2 * j + 1];
        }
        p0 += __shfl_xor_sync(0xffffffffu, p0, 1);
        p0 += __shfl_xor_sync(0xffffffffu, p0, 2);
        p1 += __shfl_xor_sync(0xffffffffu, p1, 1);
        p1 += __shfl_xor_sync(0xffffffffu, p1, 2);
        if ((lane & 3) == 0) {
            const int r0 = wm * 64 + i * 16 + (lane >> 2);
            red[r0 * 4 + wn]       = p0;
            red[(r0 + 8) * 4 + wn] = p1;
        }
    }
    __syncthreads();
    if (tid < 256) {
        float s = red[tid * 4] + red[tid * 4 + 1] + red[tid * 4 + 2] + red[tid * 4 + 3];
        g_scores_part[(size_t)kt * (B_ * S_) + mt * 256 + tid] = s;
    }
}

// ---------------- K3: softmax over S per batch ------------------------------
__global__ void softmax_kernel() {
    const int b = blockIdx.x;
    const int tid = threadIdx.x;   // 256
    __shared__ float sbuf[256];

    float m = -1e30f;
    for (int i = tid; i < S_; i += 256) {
        float v = g_scores_part[0 * B_ * S_ + b * S_ + i]
                + g_scores_part[1 * B_ * S_ + b * S_ + i]
                + g_scores_part[2 * B_ * S_ + b * S_ + i]
                + g_scores_part[3 * B_ * S_ + b * S_ + i];
        g_weights[b * S_ + i] = v;
        m = fmaxf(m, v);
    }
    sbuf[tid] = m; __syncthreads();
    for (int o = 128; o > 0; o >>= 1) {
        if (tid < o) sbuf[tid] = fmaxf(sbuf[tid], sbuf[tid + o]);
        __syncthreads();
    }
    m = sbuf[0]; __syncthreads();

    float sum = 0.f;
    for (int i = tid; i < S_; i += 256) {
        float e = __expf(g_weights[b * S_ + i] - m);
        g_weights[b * S_ + i] = e;
        sum += e;
    }
    sbuf[tid] = sum; __syncthreads();
    for (int o = 128; o > 0; o >>= 1) {
        if (tid < o) sbuf[tid] += sbuf[tid + o];
        __syncthreads();
    }
    float inv = __fdividef(1.f, sbuf[0]);
    for (int i = tid; i < S_; i += 256) g_weights[b * S_ + i] *= inv;
}

// ---------------- K4: partial context per 128-s chunk (fp16 enc) ------------
__global__ void context_kernel() {
    const int sc = blockIdx.x;   // 0..15
    const int b  = blockIdx.y;
    const int tid = threadIdx.x; // 256, each handles 2 h columns
    __shared__ float ws[128];
    if (tid < 128) ws[tid] = g_weights[b * S_ + sc * 128 + tid];
    __syncthreads();
    const __half2* e = (const __half2*)(g_enc_hi + ((size_t)b * S_ + sc * 128) * H_) + tid;
    float ax = 0.f, ay = 0.f;
#pragma unroll 8
    for (int s = 0; s < 128; s++) {
        float2 v = __half22float2(e[(size_t)s * (H_ / 2)]);
        ax = fmaf(ws[s], v.x, ax);
        ay = fmaf(ws[s], v.y, ay);
    }
    float* dst = &g_ctx_part[((size_t)sc * B_ + b) * H_ + 2 * tid];
    dst[0] = ax;
    dst[1] = ay;
}

// ---------------- K5: reduce partial contexts -------------------------------
__global__ void reduce_ctx(float* __restrict__ out) {
    int i = blockIdx.x * 256 + threadIdx.x;
    float s = 0.f;
#pragma unroll
    for (int ch = 0; ch < 16; ch++) s += g_ctx_part[(size_t)ch * B_ * H_ + i];
    out[i] = s;
}

extern "C" void kernel_launch(void* const* d_in, const int* in_sizes, int n_in,
                              void* d_out, int out_size) {
    const float* enc    = (const float*)d_in[0];
    const float* fin    = (const float*)d_in[1];
    const float* attn_w = (const float*)d_in[2];
    const float* attn_b = (const float*)d_in[3];
    const float* v_w    = (const float*)d_in[4];
    float* out = (float*)d_out;

    cudaFuncSetAttribute(scores_mma_kernel,
                         cudaFuncAttributeMaxDynamicSharedMemorySize, SMEM_NEED);

    convert_enc_kernel<<<65536, 256>>>(enc);
    convert_w_kernel<<<(H_ * H_) / 256, 256>>>(attn_w);
    cfin_kernel<<<B_, H_>>>(fin, attn_w, attn_b);
    scores_mma_kernel<<<dim3(4, 512), 512, SMEM_NEED>>>(v_w);
    softmax_kernel<<<B_, 256>>>();
    context_kernel<<<dim3(16, B_), 256>>>();
    reduce_ctx<<<(B_ * H_) / 256, 256>>>(out);
}